// round 12
// baseline (speedup 1.0000x reference)
#include <cuda_runtime.h>
#include <cuda_bf16.h>
#include <cstdint>
#include <math.h>

#define Nn 64
#define Ff 256
#define U 4096            // Nn*Nn
#define ROWS 128          // k-chunk rows per gemv block
#define GEMV_TPB 128      // threads per block
#define JBLK 8            // U / (GEMV_TPB*4)
#define KBLK (U / ROWS)   // 32
#define NW (ROWS / 32)    // warps (=4)
#define DEPTH 16          // cp.async pipeline stages
#define NBLK (JBLK * KBLK * 3)   // 768 blocks total

// scratch (allocation-free rule: __device__ globals; zero-initialized at load)
__device__ float    g_d    [U];        // shared pairwise distances
__device__ float    g_v1   [3 * U];    // layer-1 accumulator
__device__ unsigned g_dready[KBLK];    // ==3 when dist chunk kb ready
__device__ unsigned g_z;               // ==KBLK when v1/out zeroed
__device__ unsigned g_cnt1 [3 * JBLK]; // layer-1 completion (per b,jb)
__device__ unsigned g_cnt2 [3 * JBLK]; // layer-2 epilogue counters
__device__ unsigned g_done;            // end-of-kernel reset trigger

// ---------------- cp.async helpers ----------------
__device__ __forceinline__ void cp_async16(void* s, const void* g)
{
    unsigned int sa = (unsigned int)__cvta_generic_to_shared(s);
    asm volatile("cp.async.cg.shared.global [%0], [%1], 16;" :: "r"(sa), "l"(g));
}
__device__ __forceinline__ void cp_commit()
{
    asm volatile("cp.async.commit_group;" ::: "memory");
}
template <int N> __device__ __forceinline__ void cp_wait()
{
    asm volatile("cp.async.wait_group %0;" :: "n"(N) : "memory");
}

__device__ __forceinline__ void spin_until(unsigned* c, unsigned target)
{
    while (atomicAdd(c, 0u) < target) __nanosleep(64);
}

// ---------------------------------------------------------------------------
// One fused kernel, 768 resident blocks (all wave-1; 34KB smem -> 6 blocks/SM).
// Block (b, jb, kb):
//   phase A (jb==0 only): compute 1/3 of dist chunk kb into g_d (warp-per-pair);
//                         (b==0 also zeroes v1/out chunk kb); publish counters.
//   phase B: wait dist chunk kb -> x = mask(adj_b, g_d) -> split-K GEMV
//            through W_b1 into g_v1; publish g_cnt1[b][jb].
//   phase C: wait g_cnt1[b][kb/4]==KBLK -> x = relu(v1 chunk kb) -> split-K
//            GEMV through W_b2 into out; last block per (b,jb) applies ReLU.
//   epilogue: last of all 768 blocks resets counters for the next graph replay.
// ---------------------------------------------------------------------------
__global__ void __launch_bounds__(GEMV_TPB)
fused_all_kernel(const float* __restrict__ adj0, const float* __restrict__ adj1,
                 const float* __restrict__ adj2, const float* __restrict__ nv,
                 const float* __restrict__ w0_1, const float* __restrict__ w1_1,
                 const float* __restrict__ w2_1,
                 const float* __restrict__ w0_2, const float* __restrict__ w1_2,
                 const float* __restrict__ w2_2,
                 float* __restrict__ out)
{
    __shared__ float4 stage[DEPTH][GEMV_TPB];   // 32 KB
    __shared__ float  sv[ROWS];
    __shared__ int    sidx[ROWS];
    __shared__ int    warp_off[NW + 1];
    __shared__ int    s_last;

    const int tid  = threadIdx.x;
    const int lane = tid & 31;
    const int w    = tid >> 5;

    const int bid = blockIdx.x;
    const int jb  = bid % JBLK;
    const int kb  = (bid / JBLK) % KBLK;
    const int b   = bid / (JBLK * KBLK);

    const int i0 = kb * ROWS;
    const int j0 = jb * (GEMV_TPB * 4) + tid * 4;

    const float* adj = (b == 0) ? adj0 : (b == 1) ? adj1 : adj2;

    // ================= phase A: distances (jb==0 blocks only) ==============
    if (jb == 0) {
        if (b == 0) {
            // zero v1/out chunk kb for all branches
            #pragma unroll
            for (int bb = 0; bb < 3; bb++) {
                g_v1[bb * U + i0 + tid] = 0.0f;
                out [bb * U + i0 + tid] = 0.0f;
            }
            __threadfence();
            __syncthreads();
            if (tid == 0) atomicAdd(&g_z, 1u);
        }
        // this block computes pairs [i0 + seg_lo, i0 + seg_hi)
        const int seg_lo = (b * ROWS) / 3;
        const int seg_hi = ((b + 1) * ROWS) / 3;
        for (int p = seg_lo + w; p < seg_hi; p += NW) {
            int pair = i0 + p;
            int i = pair >> 6;
            int j = pair & 63;
            const float4* ri = (const float4*)(nv + i * Ff);
            const float4* rj = (const float4*)(nv + j * Ff);
            float4 a0 = __ldg(ri + lane);
            float4 a1 = __ldg(ri + lane + 32);
            float4 b0 = __ldg(rj + lane);
            float4 b1 = __ldg(rj + lane + 32);
            float s = 0.0f, d;
            d = a0.x - b0.x; s = fmaf(d, d, s);
            d = a0.y - b0.y; s = fmaf(d, d, s);
            d = a0.z - b0.z; s = fmaf(d, d, s);
            d = a0.w - b0.w; s = fmaf(d, d, s);
            d = a1.x - b1.x; s = fmaf(d, d, s);
            d = a1.y - b1.y; s = fmaf(d, d, s);
            d = a1.z - b1.z; s = fmaf(d, d, s);
            d = a1.w - b1.w; s = fmaf(d, d, s);
            #pragma unroll
            for (int off = 16; off > 0; off >>= 1)
                s += __shfl_down_sync(0xffffffffu, s, off);
            if (lane == 0) g_d[pair] = sqrtf(s);
        }
        __threadfence();
        __syncthreads();
        if (tid == 0) atomicAdd(&g_dready[kb], 1u);
    }

    // =============== the two GEMV phases share this lambda-ish loop =========
    #pragma unroll 1
    for (int layer = 0; layer < 2; layer++) {
        const float* W;
        float*       y;
        float        v;

        if (layer == 0) {
            // wait: dist chunk kb ready, and v1/out zeroing complete
            if (tid == 0) {
                spin_until(&g_dready[kb], 3u);
                spin_until(&g_z, (unsigned)KBLK);
            }
            __syncthreads();
            __threadfence();
            W = (b == 0) ? w0_1 : (b == 1) ? w1_1 : w2_1;
            y = g_v1;
            float dv = g_d[i0 + tid];
            v = (__ldg(adj + i0 + tid) == 1.0f) ? dv : 0.0f;
        } else {
            // wait: the 32 L1 producers of v1[b, i0..i0+ROWS)
            if (tid == 0) spin_until(&g_cnt1[b * JBLK + (kb >> 2)], (unsigned)KBLK);
            __syncthreads();
            __threadfence();
            W = (b == 0) ? w0_2 : (b == 1) ? w1_2 : w2_2;
            y = out;
            v = fmaxf(g_v1[b * U + i0 + tid], 0.0f);
        }

        // deterministic compaction of nonzero entries
        bool nz = (v != 0.0f);
        unsigned m = __ballot_sync(0xffffffffu, nz);
        if (lane == 0) warp_off[w] = __popc(m);
        __syncthreads();
        if (tid == 0) {
            int s = 0;
            #pragma unroll
            for (int ww = 0; ww < NW; ww++) {
                int c = warp_off[ww];
                warp_off[ww] = s;
                s += c;
            }
            warp_off[NW] = s;
        }
        __syncthreads();
        if (nz) {
            int p = warp_off[w] + __popc(m & ((1u << lane) - 1u));
            sv[p]   = v;
            sidx[p] = i0 + tid;
        }
        __syncthreads();
        const int cnt = warp_off[NW];

        const float* Wb = W + (size_t)j0;
        float4 acc = make_float4(0.f, 0.f, 0.f, 0.f);

        // prologue: fill pipeline (always commit, even empty groups)
        #pragma unroll
        for (int s = 0; s < DEPTH; s++) {
            if (s < cnt)
                cp_async16(&stage[s][tid], Wb + (size_t)sidx[s] * U);
            cp_commit();
        }
        // steady state
        for (int k = 0; k < cnt; k++) {
            cp_wait<DEPTH - 1>();
            float4 a = stage[k & (DEPTH - 1)][tid];
            float  c = sv[k];
            int n = k + DEPTH;
            if (n < cnt)
                cp_async16(&stage[n & (DEPTH - 1)][tid], Wb + (size_t)sidx[n] * U);
            cp_commit();
            acc.x = fmaf(c, a.x, acc.x);
            acc.y = fmaf(c, a.y, acc.y);
            acc.z = fmaf(c, a.z, acc.z);
            acc.w = fmaf(c, a.w, acc.w);
        }
        cp_wait<0>();

        float* yp = y + b * U + j0;
        atomicAdd(yp + 0, acc.x);
        atomicAdd(yp + 1, acc.y);
        atomicAdd(yp + 2, acc.z);
        atomicAdd(yp + 3, acc.w);

        __threadfence();
        __syncthreads();

        if (layer == 0) {
            if (tid == 0) atomicAdd(&g_cnt1[b * JBLK + jb], 1u);
        } else {
            if (tid == 0) {
                unsigned old = atomicAdd(&g_cnt2[b * JBLK + jb], 1u);
                s_last = (old == KBLK - 1) ? 1 : 0;
            }
            __syncthreads();
            if (s_last) {
                float r0 = __ldcg(yp + 0);
                float r1 = __ldcg(yp + 1);
                float r2 = __ldcg(yp + 2);
                float r3 = __ldcg(yp + 3);
                yp[0] = fmaxf(r0, 0.0f);
                yp[1] = fmaxf(r1, 0.0f);
                yp[2] = fmaxf(r2, 0.0f);
                yp[3] = fmaxf(r3, 0.0f);
            }
        }
        __syncthreads();
    }

    // ============ epilogue: last block resets counters for next replay ======
    if (tid == 0) {
        __threadfence();
        unsigned old = atomicAdd(&g_done, 1u);
        if (old == NBLK - 1) {
            for (int i = 0; i < KBLK; i++)     g_dready[i] = 0u;
            for (int i = 0; i < 3 * JBLK; i++) { g_cnt1[i] = 0u; g_cnt2[i] = 0u; }
            g_z = 0u;
            __threadfence();
            g_done = 0u;
            __threadfence();
        }
    }
}

extern "C" void kernel_launch(void* const* d_in, const int* in_sizes, int n_in,
                              void* d_out, int out_size)
{
    const float* adj0 = (const float*)d_in[0];
    const float* adj1 = (const float*)d_in[1];
    const float* adj2 = (const float*)d_in[2];
    const float* nv   = (const float*)d_in[3];
    const float* w0_1 = (const float*)d_in[4];
    const float* w0_2 = (const float*)d_in[5];
    const float* w1_1 = (const float*)d_in[6];
    const float* w1_2 = (const float*)d_in[7];
    const float* w2_1 = (const float*)d_in[8];
    const float* w2_2 = (const float*)d_in[9];
    float* out = (float*)d_out;

    fused_all_kernel<<<NBLK, GEMV_TPB>>>(adj0, adj1, adj2, nv,
                                         w0_1, w1_1, w2_1,
                                         w0_2, w1_2, w2_2, out);
}